// round 4
// baseline (speedup 1.0000x reference)
#include <cuda_runtime.h>
#include <cuda_bf16.h>
#include <cstdint>
#include <cfloat>

#define B_    64
#define H_    512
#define N_    16384
#define W_    64
#define DIN_  512
#define KDIM_ 1088
#define G4_   2048
#define KSPLIT_ 16
#define KPER_   68    // 1088/16

// d_out layout (floats)
#define OFF_Y   0
#define OFF_H   32768
#define OFF_C   65536
#define OFF_M   98304
#define OFF_WR  67207168
#define OFF_US  68255744
#define OFF_R   69304320

#define NBLK_PER_B 128
#define NFUSED (B_ * NBLK_PER_B)   // 8192

// scratch
__device__ float g_zp[KSPLIT_ * B_ * G4_];
__device__ float g_qn[B_ * W_];
__device__ float g_a[B_ * W_];
__device__ float g_e[B_ * W_];
__device__ float g_alpha[B_];
__device__ float g_gamma[B_];
__device__ float g_simv[NFUSED * 4];
__device__ int   g_simi[NFUSED * 4];
__device__ float g_usv[NFUSED * 5];
__device__ int   g_usi[NFUSED * 5];
__device__ int   g_idx4[B_ * 4];
__device__ float g_p4[B_ * 4];

__device__ __forceinline__ float sigmoidf_(float x) { return 1.0f / (1.0f + expf(-x)); }

// merge two sorted lists (value desc, index asc), result into (v,ix)
template<int KK>
__device__ __forceinline__ void merge2(float* v, int* ix, const float* v2, const int* i2) {
    float ov[KK]; int oi[KK]; int pa = 0, pb = 0;
#pragma unroll
    for (int t = 0; t < KK; t++) {
        bool ta;
        if (pa >= KK) ta = false;
        else if (pb >= KK) ta = true;
        else ta = (v[pa] > v2[pb]) || (v[pa] == v2[pb] && ix[pa] < i2[pb]);
        if (ta) { ov[t] = v[pa]; oi[t] = ix[pa]; pa++; }
        else    { ov[t] = v2[pb]; oi[t] = i2[pb]; pb++; }
    }
#pragma unroll
    for (int t = 0; t < KK; t++) { v[t] = ov[t]; ix[t] = oi[t]; }
}

// insert (val,n) into sorted list
template<int KK>
__device__ __forceinline__ void insert_sorted(float* lv, int* li, float v, int n) {
    if (v > lv[KK-1] || (v == lv[KK-1] && n < li[KK-1])) {
        lv[KK-1] = v; li[KK-1] = n;
#pragma unroll
        for (int p = KK-1; p > 0; p--) {
            bool up = (lv[p] > lv[p-1]) || (lv[p] == lv[p-1] && li[p] < li[p-1]);
            if (up) {
                float tv = lv[p]; lv[p] = lv[p-1]; lv[p-1] = tv;
                int   ti = li[p]; li[p] = li[p-1]; li[p-1] = ti;
            }
        }
    }
}

// ---------------------------------------------------------------------------
// K1: z partials. grid = 32 j-tiles x 16 k-splits = 512 blocks, 256 threads.
// ---------------------------------------------------------------------------
__global__ void k_gemm_z(const float* __restrict__ inp, const float* __restrict__ rprev,
                         const float* __restrict__ hprev, const float* __restrict__ Wk,
                         const float* __restrict__ Uk) {
    __shared__ __align__(16) float Xs[4][64];
    __shared__ __align__(16) float Ws[4][64];
    const int jt = blockIdx.x & 31;
    const int ks = blockIdx.x >> 5;
    const int j0 = jt * 64;
    const int kbase = ks * KPER_;
    const int t = threadIdx.x;
    const int tj = t & 15;
    const int tb = t >> 4;

    float acc[4][4];
#pragma unroll
    for (int r = 0; r < 4; r++)
#pragma unroll
        for (int c = 0; c < 4; c++) acc[r][c] = 0.0f;

    for (int cch = 0; cch < 17; cch++) {
        const int k0 = kbase + cch * 4;
        {   // X: 64b x 4k = 256 elements, one per thread
            int b = t >> 2, kk = t & 3, kg = k0 + kk;
            float v;
            if (kg < DIN_)            v = inp[b * DIN_ + kg];
            else if (kg < DIN_ + W_)  v = rprev[b * W_ + (kg - DIN_)];
            else                      v = hprev[b * H_ + (kg - DIN_ - W_)];
            Xs[kk][b] = v;
        }
        {   // W: 4k x 64j
            int kk = t >> 6, jj = t & 63, kg = k0 + kk;
            float w = (kg < DIN_ + W_) ? Wk[kg * G4_ + j0 + jj]
                                       : Uk[(kg - DIN_ - W_) * G4_ + j0 + jj];
            Ws[kk][jj] = w;
        }
        __syncthreads();
#pragma unroll
        for (int kk = 0; kk < 4; kk++) {
            float4 xv = *(const float4*)&Xs[kk][tb * 4];
            float4 wv = *(const float4*)&Ws[kk][tj * 4];
            float xr[4] = {xv.x, xv.y, xv.z, xv.w};
            float wc[4] = {wv.x, wv.y, wv.z, wv.w};
#pragma unroll
            for (int r = 0; r < 4; r++)
#pragma unroll
                for (int c = 0; c < 4; c++) acc[r][c] += xr[r] * wc[c];
        }
        __syncthreads();
    }
#pragma unroll
    for (int r = 0; r < 4; r++) {
        float4 st = make_float4(acc[r][0], acc[r][1], acc[r][2], acc[r][3]);
        *(float4*)&g_zp[ks * (B_ * G4_) + (tb * 4 + r) * G4_ + j0 + tj * 4] = st;
    }
}

// ---------------------------------------------------------------------------
// K2: reduce partials + gates
// ---------------------------------------------------------------------------
__global__ void k_gates(const float* __restrict__ cprev, const float* __restrict__ bl,
                        float* __restrict__ h_out, float* __restrict__ c_out) {
    int idx = blockIdx.x * blockDim.x + threadIdx.x;
    if (idx >= B_ * H_) return;
    int b = idx >> 9, hh = idx & 511;
    float z[4];
#pragma unroll
    for (int g = 0; g < 4; g++) z[g] = bl[g * H_ + hh];
#pragma unroll
    for (int ks = 0; ks < KSPLIT_; ks++) {
        const float* zp = g_zp + ks * (B_ * G4_) + b * G4_;
#pragma unroll
        for (int g = 0; g < 4; g++) z[g] += zp[g * H_ + hh];
    }
    float ig = sigmoidf_(z[0]);
    float fg = sigmoidf_(z[1]);
    float og = sigmoidf_(z[3]);
    float c  = fg * cprev[idx] + ig * tanhf(z[2]);
    c_out[idx] = c;
    h_out[idx] = og * tanhf(c);
}

// ---------------------------------------------------------------------------
// K3: params + derive. grid=64 (b), block=256
// ---------------------------------------------------------------------------
__global__ void k_params_derive(const float* __restrict__ h, const float* __restrict__ Wp,
                                const float* __restrict__ bp) {
    __shared__ float sh[H_];
    __shared__ float sp[194];
    __shared__ float ws[2];
    const int b = blockIdx.x, j = threadIdx.x;
    for (int k = j; k < H_; k += 256) sh[k] = h[b * H_ + k];
    __syncthreads();
    if (j < 194) {
        float acc = bp[j];
#pragma unroll 4
        for (int k = 0; k < H_; k++) acc += sh[k] * Wp[k * 194 + j];
        sp[j] = acc;
    }
    __syncthreads();
    if (j < 64) {
        float q = sp[j];
        float s = q * q;
#pragma unroll
        for (int off = 16; off > 0; off >>= 1) s += __shfl_down_sync(0xffffffffu, s, off);
        if ((j & 31) == 0) ws[j >> 5] = s;
    }
    __syncthreads();
    if (j < 64) {
        float tot = ws[0] + ws[1];
        g_qn[b * W_ + j] = sp[j] * rsqrtf(fmaxf(tot, 1e-12f));
        g_a[b * W_ + j]  = sp[W_ + j];
        g_e[b * W_ + j]  = sigmoidf_(sp[2 * W_ + j]);
        if (j == 0) {
            g_alpha[b] = sigmoidf_(sp[192]);
            g_gamma[b] = sigmoidf_(sp[193]);
        }
    }
}

// ---------------------------------------------------------------------------
// K4 (FUSED): one pass over M + usage/wr streams + in-block top4(sim)/top5(usage)
// grid = 8192 blocks (128 rows each), block = 256
// ---------------------------------------------------------------------------
__global__ void k_fused(const float* __restrict__ M, const float* __restrict__ wrp,
                        const float* __restrict__ usage,
                        float* __restrict__ Mout, float* __restrict__ wr_out,
                        float* __restrict__ us_out) {
    const int b  = blockIdx.x >> 7;
    const int n0 = (blockIdx.x & 127) << 7;
    const int tid = threadIdx.x;
    __shared__ __align__(16) float se[W_], sa[W_], sq[W_];
    __shared__ float s_sim[128];
    __shared__ float s_ag;
    __shared__ float ssv[32][4];
    __shared__ int   ssi[32][4];
    __shared__ float suv[128][5];
    __shared__ int   sui[128][5];

    if (tid < W_) { se[tid] = g_e[b * W_ + tid]; sa[tid] = g_a[b * W_ + tid]; sq[tid] = g_qn[b * W_ + tid]; }
    if (tid == 0) s_ag = g_alpha[b] * g_gamma[b];
    __syncthreads();

    const int lane = tid & 31, warp = tid >> 5;
    const int half = lane >> 4, l16 = lane & 15;
    const int rbase = warp * 2 + half;
    const size_t browoff = (size_t)b * N_ + n0;

    float4 m[8];
    float wr[8];
#pragma unroll
    for (int i = 0; i < 8; i++)
        m[i] = __ldcs((const float4*)(M + (browoff + i * 16 + rbase) * W_) + l16);
#pragma unroll
    for (int i = 0; i < 8; i++)
        wr[i] = __ldg(wrp + browoff + i * 16 + rbase);

    // usage / wr streams (128 rows per block)
    float uval = 0.0f;
    if (tid < 128) {
        uval = __ldcs(usage + browoff + tid);
        __stcs(us_out + browoff + tid, uval + 1.0f);
        __stcs(wr_out + browoff + tid, 0.0f);
    }

    const float4 e4 = *(const float4*)(se + l16 * 4);
    const float4 a4 = *(const float4*)(sa + l16 * 4);
    const float4 q4 = *(const float4*)(sq + l16 * 4);
    const float ag = s_ag;

#pragma unroll
    for (int i = 0; i < 8; i++) {
        float dot = m[i].x * q4.x + m[i].y * q4.y + m[i].z * q4.z + m[i].w * q4.w;
        float ss  = m[i].x * m[i].x + m[i].y * m[i].y + m[i].z * m[i].z + m[i].w * m[i].w;
#pragma unroll
        for (int off = 8; off > 0; off >>= 1) {
            dot += __shfl_down_sync(0xffffffffu, dot, off);
            ss  += __shfl_down_sync(0xffffffffu, ss,  off);
        }
        if (l16 == 0) s_sim[i * 16 + rbase] = dot * rsqrtf(fmaxf(ss, 1e-12f));

        const float ww = ag * wr[i];
        float4 o;
        o.x = m[i].x * (1.0f - ww * e4.x) + ww * a4.x;
        o.y = m[i].y * (1.0f - ww * e4.y) + ww * a4.y;
        o.z = m[i].z * (1.0f - ww * e4.z) + ww * a4.z;
        o.w = m[i].w * (1.0f - ww * e4.w) + ww * a4.w;
        __stcs((float4*)(Mout + (browoff + i * 16 + rbase) * W_) + l16, o);
    }
    __syncthreads();   // s_sim ready

    // init reduction lists
    if (tid >= 128 && tid < 160) {
        const int t = tid - 128;
        float lv[4]; int li[4];
#pragma unroll
        for (int j = 0; j < 4; j++) { lv[j] = -FLT_MAX; li[j] = 0x7FFFFFFF; }
#pragma unroll
        for (int j = 0; j < 4; j++) insert_sorted<4>(lv, li, s_sim[t * 4 + j], n0 + t * 4 + j);
#pragma unroll
        for (int j = 0; j < 4; j++) { ssv[t][j] = lv[j]; ssi[t][j] = li[j]; }
    }
    if (tid < 128) {
        suv[tid][0] = uval; sui[tid][0] = n0 + tid;
#pragma unroll
        for (int j = 1; j < 5; j++) { suv[tid][j] = -FLT_MAX; sui[tid][j] = 0x7FFFFFFF; }
    }
    __syncthreads();

    // tree merges: usage on threads [0,s), sim on threads [128,128+min(s,16))
#pragma unroll
    for (int s = 64; s > 0; s >>= 1) {
        if (tid < s) {
            float v[5]; int ix[5];
#pragma unroll
            for (int j = 0; j < 5; j++) { v[j] = suv[tid][j]; ix[j] = sui[tid][j]; }
            merge2<5>(v, ix, suv[tid + s], sui[tid + s]);
#pragma unroll
            for (int j = 0; j < 5; j++) { suv[tid][j] = v[j]; sui[tid][j] = ix[j]; }
        }
        if (s <= 16 && tid >= 128 && tid < 128 + s) {
            const int t = tid - 128;
            float v[4]; int ix[4];
#pragma unroll
            for (int j = 0; j < 4; j++) { v[j] = ssv[t][j]; ix[j] = ssi[t][j]; }
            merge2<4>(v, ix, ssv[t + s], ssi[t + s]);
#pragma unroll
            for (int j = 0; j < 4; j++) { ssv[t][j] = v[j]; ssi[t][j] = ix[j]; }
        }
        __syncthreads();
    }

    if (tid < 4) {
        g_simv[blockIdx.x * 4 + tid] = ssv[0][tid];
        g_simi[blockIdx.x * 4 + tid] = ssi[0][tid];
    }
    if (tid >= 8 && tid < 13) {
        g_usv[blockIdx.x * 5 + (tid - 8)] = suv[0][tid - 8];
        g_usi[blockIdx.x * 5 + (tid - 8)] = sui[0][tid - 8];
    }
}

// ---------------------------------------------------------------------------
// K5: merge sim candidates -> global top4 + softmax + r_curr. grid=64, block=128
// ---------------------------------------------------------------------------
__global__ void k_topmerge(const float* __restrict__ Mprev, float* __restrict__ r_out) {
    const int b = blockIdx.x, tid = threadIdx.x;
    __shared__ float mv[128][4];
    __shared__ int   mi[128][4];
    __shared__ int s_idx[4];
    __shared__ float s_p[4];

#pragma unroll
    for (int j = 0; j < 4; j++) {
        mv[tid][j] = g_simv[(b * 128 + tid) * 4 + j];
        mi[tid][j] = g_simi[(b * 128 + tid) * 4 + j];
    }
    __syncthreads();
#pragma unroll
    for (int s = 64; s > 0; s >>= 1) {
        if (tid < s) {
            float v[4]; int ix[4];
#pragma unroll
            for (int j = 0; j < 4; j++) { v[j] = mv[tid][j]; ix[j] = mi[tid][j]; }
            merge2<4>(v, ix, mv[tid + s], mi[tid + s]);
#pragma unroll
            for (int j = 0; j < 4; j++) { mv[tid][j] = v[j]; mi[tid][j] = ix[j]; }
        }
        __syncthreads();
    }
    if (tid == 0) {
        float vmax = mv[0][0], sum = 0.0f, ev[4];
#pragma unroll
        for (int j = 0; j < 4; j++) { ev[j] = expf(mv[0][j] - vmax); sum += ev[j]; }
        float inv = 1.0f / sum;
#pragma unroll
        for (int j = 0; j < 4; j++) {
            s_p[j] = ev[j] * inv; s_idx[j] = mi[0][j];
            g_p4[b * 4 + j] = s_p[j]; g_idx4[b * 4 + j] = mi[0][j];
        }
    }
    __syncthreads();
    if (tid < W_) {
        float r = s_p[0] * Mprev[((size_t)b * N_ + s_idx[0]) * W_ + tid]
                + s_p[1] * Mprev[((size_t)b * N_ + s_idx[1]) * W_ + tid]
                + s_p[2] * Mprev[((size_t)b * N_ + s_idx[2]) * W_ + tid]
                + s_p[3] * Mprev[((size_t)b * N_ + s_idx[3]) * W_ + tid];
        r_out[b * W_ + tid] = r;
    }
}

// ---------------------------------------------------------------------------
// K6: merge usage candidates -> lru; fix M lru row + 4 wr/us entries.
// grid=64, block=128
// ---------------------------------------------------------------------------
__global__ void k_fixup(const float* __restrict__ Mprev, const float* __restrict__ wrp,
                        float* __restrict__ Mout, float* __restrict__ wr_out,
                        float* __restrict__ us_out) {
    const int b = blockIdx.x, tid = threadIdx.x;
    __shared__ float uv[128][5];
    __shared__ int   ui[128][5];
    __shared__ int s_lru;

#pragma unroll
    for (int j = 0; j < 5; j++) {
        uv[tid][j] = g_usv[(b * 128 + tid) * 5 + j];
        ui[tid][j] = g_usi[(b * 128 + tid) * 5 + j];
    }
    __syncthreads();
#pragma unroll
    for (int s = 64; s > 0; s >>= 1) {
        if (tid < s) {
            float v[5]; int ix[5];
#pragma unroll
            for (int j = 0; j < 5; j++) { v[j] = uv[tid][j]; ix[j] = ui[tid][j]; }
            merge2<5>(v, ix, uv[tid + s], ui[tid + s]);
#pragma unroll
            for (int j = 0; j < 5; j++) { uv[tid][j] = v[j]; ui[tid][j] = ix[j]; }
        }
        __syncthreads();
    }
    if (tid == 0) {
        const int i0 = g_idx4[b * 4 + 0], i1 = g_idx4[b * 4 + 1];
        const int i2 = g_idx4[b * 4 + 2], i3 = g_idx4[b * 4 + 3];
        int lru = ui[0][0];
#pragma unroll
        for (int j = 0; j < 5; j++) {
            int c = ui[0][j];
            if (c != i0 && c != i1 && c != i2 && c != i3) { lru = c; break; }
        }
        s_lru = lru;
    }
    __syncthreads();

    const int lru = s_lru;
    if (tid < 16) {
        const float alpha = g_alpha[b], gamma = g_gamma[b];
        const float ww = alpha * (gamma * wrp[b * N_ + lru] + (1.0f - gamma));
        const size_t rowoff = ((size_t)b * N_ + lru) * W_;
        float4 mrow = *(const float4*)(Mprev + rowoff + tid * 4);
        float4 e4 = *(const float4*)(g_e + b * W_ + tid * 4);
        float4 a4 = *(const float4*)(g_a + b * W_ + tid * 4);
        float4 o;
        o.x = mrow.x * (1.0f - ww * e4.x) + ww * a4.x;
        o.y = mrow.y * (1.0f - ww * e4.y) + ww * a4.y;
        o.z = mrow.z * (1.0f - ww * e4.z) + ww * a4.z;
        o.w = mrow.w * (1.0f - ww * e4.w) + ww * a4.w;
        *(float4*)(Mout + rowoff + tid * 4) = o;
    }
    if (tid >= 32 && tid < 36) {
        const int j = tid - 32;
        const int idx = g_idx4[b * 4 + j];
        wr_out[b * N_ + idx] = g_p4[b * 4 + j];
        us_out[b * N_ + idx] = 0.0f;
    }
}

// ---------------------------------------------------------------------------
// K7: y_out = [h, r] @ Wf + bf. grid=64 (b), block=512 (j)
// ---------------------------------------------------------------------------
__global__ void k_yout(const float* __restrict__ h, const float* __restrict__ r,
                       const float* __restrict__ Wf, const float* __restrict__ bf,
                       float* __restrict__ y) {
    __shared__ float xs[H_ + W_];
    const int b = blockIdx.x;
    const int j = threadIdx.x;
    xs[j] = h[b * H_ + j];
    if (j < W_) xs[H_ + j] = r[b * W_ + j];
    __syncthreads();
    float acc = bf[j];
#pragma unroll 8
    for (int k = 0; k < H_ + W_; k++) acc += xs[k] * __ldg(Wf + k * H_ + j);
    y[b * H_ + j] = acc;
}

// ---------------------------------------------------------------------------
extern "C" void kernel_launch(void* const* d_in, const int* in_sizes, int n_in,
                              void* d_out, int out_size) {
    const float* inputs = (const float*)d_in[0];
    const float* h_prev = (const float*)d_in[1];
    const float* c_prev = (const float*)d_in[2];
    const float* M_prev = (const float*)d_in[3];
    const float* wr_prev = (const float*)d_in[4];
    const float* usage_prev = (const float*)d_in[5];
    const float* r_prev = (const float*)d_in[6];
    const float* Wk = (const float*)d_in[7];
    const float* Uk = (const float*)d_in[8];
    const float* b_lstm = (const float*)d_in[9];
    const float* Wp = (const float*)d_in[10];
    const float* bp = (const float*)d_in[11];
    const float* Wf = (const float*)d_in[12];
    const float* bf = (const float*)d_in[13];

    float* out = (float*)d_out;
    float* o_y  = out + OFF_Y;
    float* o_h  = out + OFF_H;
    float* o_c  = out + OFF_C;
    float* o_M  = out + OFF_M;
    float* o_wr = out + OFF_WR;
    float* o_us = out + OFF_US;
    float* o_r  = out + OFF_R;

    k_gemm_z<<<512, 256>>>(inputs, r_prev, h_prev, Wk, Uk);
    k_gates<<<128, 256>>>(c_prev, b_lstm, o_h, o_c);
    k_params_derive<<<64, 256>>>(o_h, Wp, bp);
    k_fused<<<NFUSED, 256>>>(M_prev, wr_prev, usage_prev, o_M, o_wr, o_us);
    k_topmerge<<<64, 128>>>(M_prev, o_r);
    k_fixup<<<64, 128>>>(M_prev, wr_prev, o_M, o_wr, o_us);
    k_yout<<<64, 512>>>(o_h, o_r, Wf, bf, o_y);
}

// round 5
// speedup vs baseline: 1.2573x; 1.2573x over previous
#include <cuda_runtime.h>
#include <cuda_bf16.h>
#include <cstdint>
#include <cfloat>

#define B_    64
#define H_    512
#define N_    16384
#define W_    64
#define DIN_  512
#define KDIM_ 1088
#define G4_   2048
#define KSPLIT_ 16
#define KPER_   68    // 1088/16

// d_out layout (floats)
#define OFF_Y   0
#define OFF_H   32768
#define OFF_C   65536
#define OFF_M   98304
#define OFF_WR  67207168
#define OFF_US  68255744
#define OFF_R   69304320

// scratch
__device__ float g_zp[KSPLIT_ * B_ * G4_];
__device__ float g_qn[B_ * W_];
__device__ float g_a[B_ * W_];
__device__ float g_e[B_ * W_];
__device__ float g_alpha[B_];
__device__ float g_gamma[B_];
__device__ float g_sim[B_ * N_];
__device__ float g_simv[512 * 4];      // 8 blocks/b * 4 candidates
__device__ int   g_simi[512 * 4];
__device__ float g_usv[1024 * 5];      // 16 blocks/b * 5 candidates
__device__ int   g_usi[1024 * 5];

__device__ __forceinline__ float sigmoidf_(float x) { return 1.0f / (1.0f + expf(-x)); }

template<int KK>
__device__ __forceinline__ void insert_sorted(float* lv, int* li, float v, int n) {
    if (v > lv[KK-1] || (v == lv[KK-1] && n < li[KK-1])) {
        lv[KK-1] = v; li[KK-1] = n;
#pragma unroll
        for (int p = KK-1; p > 0; p--) {
            bool up = (lv[p] > lv[p-1]) || (lv[p] == lv[p-1] && li[p] < li[p-1]);
            if (up) {
                float tv = lv[p]; lv[p] = lv[p-1]; lv[p-1] = tv;
                int   ti = li[p]; li[p] = li[p-1]; li[p-1] = ti;
            }
        }
    }
}

template<int KK>
__device__ __forceinline__ void merge2(float* v, int* ix, const float* v2, const int* i2) {
    float ov[KK]; int oi[KK]; int pa = 0, pb = 0;
#pragma unroll
    for (int t = 0; t < KK; t++) {
        bool ta;
        if (pa >= KK) ta = false;
        else if (pb >= KK) ta = true;
        else ta = (v[pa] > v2[pb]) || (v[pa] == v2[pb] && ix[pa] < i2[pb]);
        if (ta) { ov[t] = v[pa]; oi[t] = ix[pa]; pa++; }
        else    { ov[t] = v2[pb]; oi[t] = i2[pb]; pb++; }
    }
#pragma unroll
    for (int t = 0; t < KK; t++) { v[t] = ov[t]; ix[t] = oi[t]; }
}

// ---------------------------------------------------------------------------
// K1: z partials. grid = 32 j-tiles x 16 k-splits = 512 blocks, 256 threads.
// ---------------------------------------------------------------------------
__global__ void k_gemm_z(const float* __restrict__ inp, const float* __restrict__ rprev,
                         const float* __restrict__ hprev, const float* __restrict__ Wk,
                         const float* __restrict__ Uk) {
    __shared__ __align__(16) float Xs[4][64];
    __shared__ __align__(16) float Ws[4][64];
    const int jt = blockIdx.x & 31;
    const int ks = blockIdx.x >> 5;
    const int j0 = jt * 64;
    const int kbase = ks * KPER_;
    const int t = threadIdx.x;
    const int tj = t & 15;
    const int tb = t >> 4;

    float acc[4][4];
#pragma unroll
    for (int r = 0; r < 4; r++)
#pragma unroll
        for (int c = 0; c < 4; c++) acc[r][c] = 0.0f;

    for (int cch = 0; cch < 17; cch++) {
        const int k0 = kbase + cch * 4;
        {
            int b = t >> 2, kk = t & 3, kg = k0 + kk;
            float v;
            if (kg < DIN_)            v = inp[b * DIN_ + kg];
            else if (kg < DIN_ + W_)  v = rprev[b * W_ + (kg - DIN_)];
            else                      v = hprev[b * H_ + (kg - DIN_ - W_)];
            Xs[kk][b] = v;
        }
        {
            int kk = t >> 6, jj = t & 63, kg = k0 + kk;
            float w = (kg < DIN_ + W_) ? Wk[kg * G4_ + j0 + jj]
                                       : Uk[(kg - DIN_ - W_) * G4_ + j0 + jj];
            Ws[kk][jj] = w;
        }
        __syncthreads();
#pragma unroll
        for (int kk = 0; kk < 4; kk++) {
            float4 xv = *(const float4*)&Xs[kk][tb * 4];
            float4 wv = *(const float4*)&Ws[kk][tj * 4];
            float xr[4] = {xv.x, xv.y, xv.z, xv.w};
            float wc[4] = {wv.x, wv.y, wv.z, wv.w};
#pragma unroll
            for (int r = 0; r < 4; r++)
#pragma unroll
                for (int c = 0; c < 4; c++) acc[r][c] += xr[r] * wc[c];
        }
        __syncthreads();
    }
#pragma unroll
    for (int r = 0; r < 4; r++) {
        float4 st = make_float4(acc[r][0], acc[r][1], acc[r][2], acc[r][3]);
        *(float4*)&g_zp[ks * (B_ * G4_) + (tb * 4 + r) * G4_ + j0 + tj * 4] = st;
    }
}

// ---------------------------------------------------------------------------
// K2 (merged): z reduce + gates + params + derive. grid=64 (b), block=256
// ---------------------------------------------------------------------------
__global__ void k_hparams(const float* __restrict__ cprev, const float* __restrict__ bl,
                          const float* __restrict__ Wp, const float* __restrict__ bp,
                          float* __restrict__ h_out, float* __restrict__ c_out) {
    __shared__ float zz[G4_];
    __shared__ float sh[H_];
    __shared__ float sp[194];
    __shared__ float ws[2];
    const int b = blockIdx.x, tid = threadIdx.x;

    // reduce z partials
#pragma unroll
    for (int i = 0; i < 8; i++) {
        const int hh = tid + i * 256;
        float z = bl[hh];
#pragma unroll
        for (int ks = 0; ks < KSPLIT_; ks++)
            z += g_zp[ks * (B_ * G4_) + b * G4_ + hh];
        zz[hh] = z;
    }
    __syncthreads();

    // gates
#pragma unroll
    for (int i = 0; i < 2; i++) {
        const int hh = tid + i * 256;
        float ig = sigmoidf_(zz[hh]);
        float fg = sigmoidf_(zz[H_ + hh]);
        float og = sigmoidf_(zz[3 * H_ + hh]);
        float c  = fg * cprev[b * H_ + hh] + ig * tanhf(zz[2 * H_ + hh]);
        float h  = og * tanhf(c);
        c_out[b * H_ + hh] = c;
        h_out[b * H_ + hh] = h;
        sh[hh] = h;
    }
    __syncthreads();

    // params
    if (tid < 194) {
        float acc = bp[tid];
#pragma unroll 4
        for (int k = 0; k < H_; k++) acc += sh[k] * Wp[k * 194 + tid];
        sp[tid] = acc;
    }
    __syncthreads();

    // derive
    if (tid < 64) {
        float q = sp[tid];
        float s = q * q;
#pragma unroll
        for (int off = 16; off > 0; off >>= 1) s += __shfl_down_sync(0xffffffffu, s, off);
        if ((tid & 31) == 0) ws[tid >> 5] = s;
    }
    __syncthreads();
    if (tid < 64) {
        float tot = ws[0] + ws[1];
        g_qn[b * W_ + tid] = sp[tid] * rsqrtf(fmaxf(tot, 1e-12f));
        g_a[b * W_ + tid]  = sp[W_ + tid];
        g_e[b * W_ + tid]  = sigmoidf_(sp[2 * W_ + tid]);
        if (tid == 0) {
            g_alpha[b] = sigmoidf_(sp[192]);
            g_gamma[b] = sigmoidf_(sp[193]);
        }
    }
}

// ---------------------------------------------------------------------------
// K3 (FUSED, R3-proven): one pass over M: sim + base M update.
// grid = 8192 blocks (128 rows each), block = 256.
// ---------------------------------------------------------------------------
__global__ void k_fused(const float* __restrict__ M, const float* __restrict__ wrp,
                        float* __restrict__ Mout) {
    const int b  = blockIdx.x >> 7;
    const int n0 = (blockIdx.x & 127) << 7;
    const int tid = threadIdx.x;
    __shared__ __align__(16) float se[W_], sa[W_], sq[W_];
    __shared__ float s_sim[128];
    __shared__ float s_ag;
    if (tid < W_) { se[tid] = g_e[b * W_ + tid]; sa[tid] = g_a[b * W_ + tid]; sq[tid] = g_qn[b * W_ + tid]; }
    if (tid == 0) s_ag = g_alpha[b] * g_gamma[b];
    __syncthreads();

    const int lane = tid & 31, warp = tid >> 5;
    const int half = lane >> 4, l16 = lane & 15;
    const int rbase = warp * 2 + half;
    const size_t browoff = (size_t)b * N_ + n0;

    float4 m[8];
    float wr[8];
#pragma unroll
    for (int i = 0; i < 8; i++)
        m[i] = __ldcs((const float4*)(M + (browoff + i * 16 + rbase) * W_) + l16);
#pragma unroll
    for (int i = 0; i < 8; i++)
        wr[i] = __ldg(wrp + browoff + i * 16 + rbase);

    const float4 e4 = *(const float4*)(se + l16 * 4);
    const float4 a4 = *(const float4*)(sa + l16 * 4);
    const float4 q4 = *(const float4*)(sq + l16 * 4);
    const float ag = s_ag;

#pragma unroll
    for (int i = 0; i < 8; i++) {
        float dot = m[i].x * q4.x + m[i].y * q4.y + m[i].z * q4.z + m[i].w * q4.w;
        float ss  = m[i].x * m[i].x + m[i].y * m[i].y + m[i].z * m[i].z + m[i].w * m[i].w;
#pragma unroll
        for (int off = 8; off > 0; off >>= 1) {
            dot += __shfl_down_sync(0xffffffffu, dot, off);
            ss  += __shfl_down_sync(0xffffffffu, ss,  off);
        }
        if (l16 == 0) s_sim[i * 16 + rbase] = dot * rsqrtf(fmaxf(ss, 1e-12f));

        const float ww = ag * wr[i];
        float4 o;
        o.x = m[i].x * (1.0f - ww * e4.x) + ww * a4.x;
        o.y = m[i].y * (1.0f - ww * e4.y) + ww * a4.y;
        o.z = m[i].z * (1.0f - ww * e4.z) + ww * a4.z;
        o.w = m[i].w * (1.0f - ww * e4.w) + ww * a4.w;
        __stcs((float4*)(Mout + (browoff + i * 16 + rbase) * W_) + l16, o);
    }
    __syncthreads();
    if (tid < 128) g_sim[browoff + tid] = s_sim[tid];
}

// ---------------------------------------------------------------------------
// K4 (heterogeneous): blocks [0,512): top-4 of sim per (b, chunk of 2048).
//                     blocks [512,1536): usage stream + block top-5 of usage_prev.
// block = 256
// ---------------------------------------------------------------------------
__global__ void k_sel(const float* __restrict__ usprev,
                      float* __restrict__ wr_out, float* __restrict__ us_out) {
    const int tid = threadIdx.x;

    if (blockIdx.x < 512) {
        // ---- top-4 of sim ----
        const int b = blockIdx.x >> 3, chunk = blockIdx.x & 7;
        __shared__ float sv[256][4];
        __shared__ int   si[256][4];
        float lv[4]; int li[4];
#pragma unroll
        for (int j = 0; j < 4; j++) { lv[j] = -FLT_MAX; li[j] = 0x7FFFFFFF; }
        const float* simb = g_sim + b * N_ + chunk * 2048;
        const int nbase = chunk * 2048;
#pragma unroll
        for (int i = 0; i < 8; i++) {
            int nl = tid + i * 256;
            insert_sorted<4>(lv, li, simb[nl], nbase + nl);
        }
#pragma unroll
        for (int j = 0; j < 4; j++) { sv[tid][j] = lv[j]; si[tid][j] = li[j]; }
        __syncthreads();
        for (int s = 128; s > 0; s >>= 1) {
            if (tid < s) {
                float v[4]; int ix[4];
#pragma unroll
                for (int j = 0; j < 4; j++) { v[j] = sv[tid][j]; ix[j] = si[tid][j]; }
                merge2<4>(v, ix, sv[tid + s], si[tid + s]);
#pragma unroll
                for (int j = 0; j < 4; j++) { sv[tid][j] = v[j]; si[tid][j] = ix[j]; }
            }
            __syncthreads();
        }
        if (tid < 4) {
            g_simv[blockIdx.x * 4 + tid] = sv[0][tid];
            g_simi[blockIdx.x * 4 + tid] = si[0][tid];
        }
    } else {
        // ---- usage stream + top-5 ----
        const int blk = blockIdx.x - 512;
        const int b = blk >> 4, chunk = blk & 15;
        const int n0 = chunk * 1024 + tid * 4;
        __shared__ float uv[256][5];
        __shared__ int   ui[256][5];

        float4 up = __ldcs((const float4*)(usprev + b * N_ + n0));
        __stcs((float4*)(us_out + b * N_ + n0),
               make_float4(up.x + 1.0f, up.y + 1.0f, up.z + 1.0f, up.w + 1.0f));
        __stcs((float4*)(wr_out + b * N_ + n0), make_float4(0.f, 0.f, 0.f, 0.f));

        float lv[5]; int li[5];
#pragma unroll
        for (int j = 0; j < 5; j++) { lv[j] = -FLT_MAX; li[j] = 0x7FFFFFFF; }
        insert_sorted<5>(lv, li, up.x, n0 + 0);
        insert_sorted<5>(lv, li, up.y, n0 + 1);
        insert_sorted<5>(lv, li, up.z, n0 + 2);
        insert_sorted<5>(lv, li, up.w, n0 + 3);
#pragma unroll
        for (int j = 0; j < 5; j++) { uv[tid][j] = lv[j]; ui[tid][j] = li[j]; }
        __syncthreads();
        for (int s = 128; s > 0; s >>= 1) {
            if (tid < s) {
                float v[5]; int ix[5];
#pragma unroll
                for (int j = 0; j < 5; j++) { v[j] = uv[tid][j]; ix[j] = ui[tid][j]; }
                merge2<5>(v, ix, uv[tid + s], ui[tid + s]);
#pragma unroll
                for (int j = 0; j < 5; j++) { uv[tid][j] = v[j]; ui[tid][j] = ix[j]; }
            }
            __syncthreads();
        }
        if (tid < 5) {
            g_usv[blk * 5 + tid] = uv[0][tid];
            g_usi[blk * 5 + tid] = ui[0][tid];
        }
    }
}

// ---------------------------------------------------------------------------
// K5 (final): per-b: merge sim top4 + softmax; merge usage top5 -> lru;
// r_curr; fix M lru row; fix wr/us at top4; y_out. grid=64, block=512.
// ---------------------------------------------------------------------------
__global__ void k_final(const float* __restrict__ Mprev, const float* __restrict__ wrp,
                        const float* __restrict__ h, const float* __restrict__ Wf,
                        const float* __restrict__ bf,
                        float* __restrict__ Mout, float* __restrict__ wr_out,
                        float* __restrict__ us_out, float* __restrict__ r_out,
                        float* __restrict__ y) {
    const int b = blockIdx.x, tid = threadIdx.x;
    __shared__ float xs[H_];
    __shared__ float s_r[W_];
    __shared__ float s_p[4];
    __shared__ int   s_idx[4];
    __shared__ float s_uv[5];
    __shared__ int   s_ui[5];
    __shared__ int   s_lru;

    // phase A: candidate merges on two threads; others stage h
    xs[tid] = h[b * H_ + tid];
    if (tid == 0) {
        float lv[4]; int li[4];
#pragma unroll
        for (int j = 0; j < 4; j++) { lv[j] = -FLT_MAX; li[j] = 0x7FFFFFFF; }
        for (int c = 0; c < 32; c++)
            insert_sorted<4>(lv, li, g_simv[b * 32 + c], g_simi[b * 32 + c]);
        float vmax = lv[0], sum = 0.0f, ev[4];
#pragma unroll
        for (int j = 0; j < 4; j++) { ev[j] = expf(lv[j] - vmax); sum += ev[j]; }
        float inv = 1.0f / sum;
#pragma unroll
        for (int j = 0; j < 4; j++) { s_p[j] = ev[j] * inv; s_idx[j] = li[j]; }
    } else if (tid == 32) {
        float lv[5]; int li[5];
#pragma unroll
        for (int j = 0; j < 5; j++) { lv[j] = -FLT_MAX; li[j] = 0x7FFFFFFF; }
        for (int c = 0; c < 80; c++)
            insert_sorted<5>(lv, li, g_usv[b * 80 + c], g_usi[b * 80 + c]);
#pragma unroll
        for (int j = 0; j < 5; j++) { s_uv[j] = lv[j]; s_ui[j] = li[j]; }
    }
    __syncthreads();

    // phase B: lru pick, r_curr, wr/us fixups
    if (tid == 0) {
        int lru = s_ui[0];
#pragma unroll
        for (int j = 0; j < 5; j++) {
            int c = s_ui[j];
            if (c != s_idx[0] && c != s_idx[1] && c != s_idx[2] && c != s_idx[3]) { lru = c; break; }
        }
        s_lru = lru;
    }
    if (tid >= 128 && tid < 192) {
        const int w = tid - 128;
        float r = s_p[0] * Mprev[((size_t)b * N_ + s_idx[0]) * W_ + w]
                + s_p[1] * Mprev[((size_t)b * N_ + s_idx[1]) * W_ + w]
                + s_p[2] * Mprev[((size_t)b * N_ + s_idx[2]) * W_ + w]
                + s_p[3] * Mprev[((size_t)b * N_ + s_idx[3]) * W_ + w];
        s_r[w] = r;
        r_out[b * W_ + w] = r;
    }
    if (tid >= 224 && tid < 228) {
        const int j = tid - 224;
        const int idx = s_idx[j];
        wr_out[b * N_ + idx] = s_p[j];
        us_out[b * N_ + idx] = 0.0f;
    }
    __syncthreads();

    // phase C: lru row fix + y_out
    if (tid >= 64 && tid < 80) {
        const int k = tid - 64;
        const int lru = s_lru;
        const float alpha = g_alpha[b], gamma = g_gamma[b];
        const float ww = alpha * (gamma * wrp[b * N_ + lru] + (1.0f - gamma));
        const size_t rowoff = ((size_t)b * N_ + lru) * W_;
        float4 mrow = *(const float4*)(Mprev + rowoff + k * 4);
        float4 e4 = *(const float4*)(g_e + b * W_ + k * 4);
        float4 a4 = *(const float4*)(g_a + b * W_ + k * 4);
        float4 o;
        o.x = mrow.x * (1.0f - ww * e4.x) + ww * a4.x;
        o.y = mrow.y * (1.0f - ww * e4.y) + ww * a4.y;
        o.z = mrow.z * (1.0f - ww * e4.z) + ww * a4.z;
        o.w = mrow.w * (1.0f - ww * e4.w) + ww * a4.w;
        *(float4*)(Mout + rowoff + k * 4) = o;
    }

    float acc = bf[tid];
#pragma unroll 8
    for (int k = 0; k < H_; k++) acc += xs[k] * __ldg(Wf + k * H_ + tid);
#pragma unroll 8
    for (int k = 0; k < W_; k++) acc += s_r[k] * __ldg(Wf + (H_ + k) * H_ + tid);
    y[b * H_ + tid] = acc;
}

// ---------------------------------------------------------------------------
extern "C" void kernel_launch(void* const* d_in, const int* in_sizes, int n_in,
                              void* d_out, int out_size) {
    const float* inputs = (const float*)d_in[0];
    const float* h_prev = (const float*)d_in[1];
    const float* c_prev = (const float*)d_in[2];
    const float* M_prev = (const float*)d_in[3];
    const float* wr_prev = (const float*)d_in[4];
    const float* usage_prev = (const float*)d_in[5];
    const float* r_prev = (const float*)d_in[6];
    const float* Wk = (const float*)d_in[7];
    const float* Uk = (const float*)d_in[8];
    const float* b_lstm = (const float*)d_in[9];
    const float* Wp = (const float*)d_in[10];
    const float* bp = (const float*)d_in[11];
    const float* Wf = (const float*)d_in[12];
    const float* bf = (const float*)d_in[13];

    float* out = (float*)d_out;
    float* o_y  = out + OFF_Y;
    float* o_h  = out + OFF_H;
    float* o_c  = out + OFF_C;
    float* o_M  = out + OFF_M;
    float* o_wr = out + OFF_WR;
    float* o_us = out + OFF_US;
    float* o_r  = out + OFF_R;

    k_gemm_z<<<512, 256>>>(inputs, r_prev, h_prev, Wk, Uk);
    k_hparams<<<64, 256>>>(c_prev, b_lstm, Wp, bp, o_h, o_c);
    k_fused<<<8192, 256>>>(M_prev, wr_prev, o_M);
    k_sel<<<1536, 256>>>(usage_prev, o_wr, o_us);
    k_final<<<64, 512>>>(M_prev, wr_prev, o_h, Wf, bf, o_M, o_wr, o_us, o_r, o_y);
}